// round 10
// baseline (speedup 1.0000x reference)
#include <cuda_runtime.h>
#include <math.h>

#define NQ   12
#define DIM  4096
#define NL   4
#define TPB  256

// SU(2)-compressed fused RZ*RY*RX gate per (layer, wire): row0 only,
// (u00r, u00i, u01r, u01i). Row1 = (-conj(u01), conj(u00)) derived in-kernel.
__device__ float4 g_U4[NL * NQ];

__global__ void precompute_gates(const float* __restrict__ qw) {
    int id = threadIdx.x;
    if (id >= NL * NQ) return;
    float a = qw[3 * id + 0];
    float b = qw[3 * id + 1];
    float g = qw[3 * id + 2];
    float cA = cosf(0.5f * a), sA = sinf(0.5f * a);
    float cB = cosf(0.5f * b), sB = sinf(0.5f * b);
    float cC = cosf(0.5f * g), sC = sinf(0.5f * g);
    float m00r =  cB * cA, m00i =  sB * sA;
    float m01r = -sB * cA, m01i = -cB * sA;
    float u00r = cC * m00r + sC * m00i, u00i = cC * m00i - sC * m00r;
    float u01r = cC * m01r + sC * m01i, u01i = cC * m01i - sC * m01r;
    g_U4[id] = make_float4(u00r, u00i, u01r, u01i);
}

// phys address (element index) of logical amp under layout "active = {8..11}"
__device__ __forceinline__ int physHIGH(int x) {
    return ((x & 0xFF) << 4) | (((x >> 8) ^ x) & 15);
}

__device__ __forceinline__ float2 cmul(float2 a, float2 b) {
    return make_float2(a.x * b.x - a.y * b.y, a.x * b.y + a.y * b.x);
}

// Apply fused SU(2) gate on register-slot bit bb of array rr;
// ua = (u00r,u00i,u01r,u01i); row1 = (-u01r, u01i, u00r, -u00i) via modifiers.
#define APPLY_GATE(bb, ua, rr) do {                                          \
    _Pragma("unroll")                                                        \
    for (int m = 0; m < 8; m++) {                                            \
        const int lowm = (1 << (bb)) - 1;                                    \
        const int i0 = ((m & ~lowm) << 1) | (m & lowm);                      \
        const int i1 = i0 | (1 << (bb));                                     \
        float2 v0 = rr[i0], v1 = rr[i1];                                     \
        float2 n0, n1;                                                       \
        n0.x =  ua.x*v0.x - ua.y*v0.y + ua.z*v1.x - ua.w*v1.y;               \
        n0.y =  ua.x*v0.y + ua.y*v0.x + ua.z*v1.y + ua.w*v1.x;               \
        n1.x = -ua.z*v0.x - ua.w*v0.y + ua.x*v1.x + ua.y*v1.y;               \
        n1.y = -ua.z*v0.y + ua.w*v0.x + ua.x*v1.y - ua.y*v1.x;               \
        rr[i0] = n0; rr[i1] = n1;                                            \
    }                                                                        \
} while (0)

// Walsh epilogue for one sample's register tile rr -> W7, W12, W14, W15
#define WALSH(rr, W7v, W12v, W14v, W15v) do {                                \
    float pr[16];                                                            \
    _Pragma("unroll")                                                        \
    for (int s = 0; s < 16; s++) {                                           \
        float2 v = rr[s];                                                    \
        pr[s] = v.x * v.x + v.y * v.y;                                       \
    }                                                                        \
    float P[8], M[8];                                                        \
    _Pragma("unroll")                                                        \
    for (int u = 0; u < 8; u++) {                                            \
        P[u] = pr[2 * u] + pr[2 * u + 1];                                    \
        M[u] = pr[2 * u] - pr[2 * u + 1];                                    \
    }                                                                        \
    W7v = 0.f; W12v = 0.f; W14v = 0.f; W15v = 0.f;                           \
    _Pragma("unroll")                                                        \
    for (int u = 0; u < 8; u++) {                                            \
        if (__popc(u) & 1)      { W15v -= M[u]; W14v -= P[u]; }              \
        else                    { W15v += M[u]; W14v += P[u]; }              \
        if (__popc(u >> 1) & 1) W12v -= P[u]; else W12v += P[u];             \
        if (__popc(u & 3) & 1)  W7v  -= M[u]; else W7v  += M[u];             \
    }                                                                        \
} while (0)

__global__ __launch_bounds__(TPB, 2) void qsim(const float* __restrict__ x,
                                               const float* __restrict__ dw,
                                               const float* __restrict__ db,
                                               float* __restrict__ out) {
    // Dynamic smem: two 32KB states (one per sample handled by this CTA)
    extern __shared__ float2 s_psi[];       // [2 * DIM]

    __shared__ float4 s_U4[NL * NQ];        // SU(2)-compressed gates
    __shared__ float  s_x[2 * NQ];
    __shared__ float2 s_w[2][NQ][2];        // per-sample local 2-vectors (layer 0 folded)
    __shared__ float  s_scalar[4];
    __shared__ float  s_red[2][8 * NQ];
    __shared__ float  s_q[2][NQ];

    const int t = threadIdx.x;
    const int bidx = blockIdx.x;

    for (int i = t; i < NL * NQ; i += TPB) s_U4[i] = g_U4[i];
    if (t < 2 * NQ) s_x[t] = x[bidx * 2 * NQ + t];
    __syncthreads();

    if (t < 2) {
        float ss = 0.f, ma = 0.f;
        #pragma unroll
        for (int w = 0; w < NQ; w++) {
            float v = s_x[t * NQ + w];
            ss += v * v;
            ma = fmaxf(ma, fabsf(v));
        }
        float rr = rsqrtf(fmaxf(ss, 1e-12f));
        s_scalar[2 * t] = rr;
        s_scalar[2 * t + 1] = ma * rr;
    }
    __syncthreads();
    if (t < 2 * NQ) {
        int smp = (t < NQ) ? 0 : 1;
        int w = t - smp * NQ;
        float rr = s_scalar[2 * smp], m = s_scalar[2 * smp + 1];
        float ang = 3.14159265358979f * (s_x[t] * rr) / (m + 1e-8f);
        float c = cosf(0.5f * ang);
        float s = sinf(0.5f * ang);
        float4 ua = s_U4[w];                // layer-0 gate for wire w
        int p = 11 - w;                     // wire w lives at bit position 11-w
        s_w[smp][p][0] = make_float2( ua.x * c + ua.z * s,  ua.y * c + ua.w * s);
        s_w[smp][p][1] = make_float2(-ua.z * c + ua.x * s,  ua.w * c - ua.y * s);
    }
    __syncthreads();

    float2 r0[16], r1[16];                  // 16 amps/thread per sample
    const int storeBase = (t << 4) | (t & 15);    // store: addr = storeBase ^ s

    // ---------- init in HIGH ownership: L = (s<<8)|t, amp = prod of w[bit]
    #pragma unroll
    for (int smp = 0; smp < 2; smp++) {
        float2 ct = s_w[smp][0][t & 1];
        #pragma unroll
        for (int p = 1; p < 8; p++) ct = cmul(ct, s_w[smp][p][(t >> p) & 1]);
        float2 m01[4], m23[4], ctm[4];
        #pragma unroll
        for (int a = 0; a < 4; a++) {
            m01[a] = cmul(s_w[smp][8][a & 1],  s_w[smp][9][(a >> 1) & 1]);
            m23[a] = cmul(s_w[smp][10][a & 1], s_w[smp][11][(a >> 1) & 1]);
        }
        #pragma unroll
        for (int a = 0; a < 4; a++) ctm[a] = cmul(ct, m01[a]);
        if (smp == 0) {
            #pragma unroll
            for (int s = 0; s < 16; s++) {
                r0[s] = cmul(ctm[s & 3], m23[s >> 2]);
                s_psi[storeBase ^ s] = r0[s];
            }
        } else {
            #pragma unroll
            for (int s = 0; s < 16; s++) {
                r1[s] = cmul(ctm[s & 3], m23[s >> 2]);
                s_psi[DIM + (storeBase ^ s)] = r1[s];
            }
        }
    }
    __syncthreads();

    #pragma unroll 1
    for (int layer = 1; layer < NL; layer++) {
        // ---------- pass MID: active positions {4..7}; load HIGH layout w/ CNOT perm folded
        {
            int T  = ((t & 0xF0) << 4) | (t & 15);
            int Xt = T ^ (T >> 1) ^ ((t & 1) ? 0xC00 : 0);
            int base = physHIGH(Xt & 0xFFF);
            #pragma unroll
            for (int s = 0; s < 16; s++) {
                int Xs = ((s << 4) ^ (s << 3)) & 0xFFF;
                int a = base ^ physHIGH(Xs);
                r0[s] = s_psi[a];
                r1[s] = s_psi[DIM + a];
            }
        }
        {
            const float4 a4 = s_U4[layer * NQ + 7];
            APPLY_GATE(0, a4, r0);  APPLY_GATE(0, a4, r1);   // pos 4 = wire 7
            const float4 a5 = s_U4[layer * NQ + 6];
            APPLY_GATE(1, a5, r0);  APPLY_GATE(1, a5, r1);   // pos 5 = wire 6
            const float4 a6 = s_U4[layer * NQ + 5];
            APPLY_GATE(2, a6, r0);  APPLY_GATE(2, a6, r1);   // pos 6 = wire 5
            const float4 a7 = s_U4[layer * NQ + 4];
            APPLY_GATE(3, a7, r0);  APPLY_GATE(3, a7, r1);   // pos 7 = wire 4
        }
        __syncthreads();               // all loads done before stores clobber
        #pragma unroll
        for (int s = 0; s < 16; s++) {
            s_psi[storeBase ^ s] = r0[s];
            s_psi[DIM + (storeBase ^ s)] = r1[s];
        }
        __syncthreads();

        // ---------- pass LOW: active {0..3}; load from MID layout
        {
            int base = ((t & 0xF0) << 4) | (t & 15);
            #pragma unroll
            for (int s = 0; s < 16; s++) {
                int a = base ^ ((s << 4) | s);
                r0[s] = s_psi[a];
                r1[s] = s_psi[DIM + a];
            }
        }
        {
            const float4 a0 = s_U4[layer * NQ + 11];
            APPLY_GATE(0, a0, r0);  APPLY_GATE(0, a0, r1);   // pos 0 = wire 11
            const float4 a1 = s_U4[layer * NQ + 10];
            APPLY_GATE(1, a1, r0);  APPLY_GATE(1, a1, r1);
            const float4 a2 = s_U4[layer * NQ + 9];
            APPLY_GATE(2, a2, r0);  APPLY_GATE(2, a2, r1);
            const float4 a3 = s_U4[layer * NQ + 8];
            APPLY_GATE(3, a3, r0);  APPLY_GATE(3, a3, r1);
        }
        __syncthreads();
        #pragma unroll
        for (int s = 0; s < 16; s++) {
            s_psi[storeBase ^ s] = r0[s];
            s_psi[DIM + (storeBase ^ s)] = r1[s];
        }
        __syncthreads();

        // ---------- pass HIGH: active {8..11}; load from LOW layout
        {
            int base = t ^ ((t >> 4) & 15);
            #pragma unroll
            for (int s = 0; s < 16; s++) {
                int a = base ^ (s << 8);
                r0[s] = s_psi[a];
                r1[s] = s_psi[DIM + a];
            }
        }
        {
            const float4 a8 = s_U4[layer * NQ + 3];
            APPLY_GATE(0, a8, r0);  APPLY_GATE(0, a8, r1);   // pos 8 = wire 3
            const float4 a9 = s_U4[layer * NQ + 2];
            APPLY_GATE(1, a9, r0);  APPLY_GATE(1, a9, r1);
            const float4 a10 = s_U4[layer * NQ + 1];
            APPLY_GATE(2, a10, r0); APPLY_GATE(2, a10, r1);
            const float4 a11 = s_U4[layer * NQ + 0];
            APPLY_GATE(3, a11, r0); APPLY_GATE(3, a11, r1);
        }
        if (layer < NL - 1) {
            __syncthreads();
            #pragma unroll
            for (int s = 0; s < 16; s++) {
                s_psi[storeBase ^ s] = r0[s];
                s_psi[DIM + (storeBase ^ s)] = r1[s];
            }
            __syncthreads();
        }
        // layer-boundary CNOT ring folds into next MID load / epilogue index map
    }

    // ---------- epilogue: Walsh-transform signed probability sums, both samples
    float W7a, W12a, W14a, W15a, W7b, W12b, W14b, W15b;
    WALSH(r0, W7a, W12a, W14a, W15a);
    WALSH(r1, W7b, W12b, W14b, W15b);

    int xt = t ^ ((__popc(t) & 1) ? 0xC00 : 0);
    xt ^= xt >> 1; xt ^= xt >> 2; xt ^= xt >> 4; xt ^= xt >> 8;

    const int lane = t & 31, warp = t >> 5;
    #pragma unroll
    for (int w = 0; w < NQ; w++) {
        const int p = 11 - w;
        float Wa = (p == 11) ? W7a : (p == 10) ? W12a : (p == 9) ? W14a : W15a;
        float Wb = (p == 11) ? W7b : (p == 10) ? W12b : (p == 9) ? W14b : W15b;
        float sgn = ((xt >> p) & 1) ? -1.f : 1.f;
        float va = sgn * Wa;
        float vb = sgn * Wb;
        #pragma unroll
        for (int off = 16; off; off >>= 1) {
            va += __shfl_down_sync(0xffffffffu, va, off);
            vb += __shfl_down_sync(0xffffffffu, vb, off);
        }
        if (lane == 0) {
            s_red[0][warp * NQ + w] = va;
            s_red[1][warp * NQ + w] = vb;
        }
    }
    __syncthreads();
    if (t < 2 * NQ) {
        int smp = (t < NQ) ? 0 : 1;
        int w = t - smp * NQ;
        float qv = 0.f;
        #pragma unroll
        for (int wp = 0; wp < 8; wp++) qv += s_red[smp][wp * NQ + w];
        s_q[smp][w] = qv;
    }
    __syncthreads();
    if (t < 2 * NQ) {
        int smp = (t < NQ) ? 0 : 1;
        int o = t - smp * NQ;
        float acc = db[o];
        #pragma unroll
        for (int w = 0; w < NQ; w++) acc += s_q[smp][w] * dw[w * NQ + o];
        out[(bidx * 2 + smp) * NQ + o] = tanhf(acc);
    }
}

extern "C" void kernel_launch(void* const* d_in, const int* in_sizes, int n_in,
                              void* d_out, int out_size) {
    const float* x  = (const float*)d_in[0];
    const float* qw = (const float*)d_in[1];
    const float* dw = (const float*)d_in[2];
    const float* db = (const float*)d_in[3];
    float* out = (float*)d_out;

    int batch = in_sizes[0] / NQ;

    const int dyn_smem = 2 * DIM * (int)sizeof(float2);   // 64 KB (two states)
    cudaFuncSetAttribute(qsim, cudaFuncAttributeMaxDynamicSharedMemorySize, dyn_smem);

    precompute_gates<<<1, 64>>>(qw);
    qsim<<<batch / 2, TPB, dyn_smem>>>(x, dw, db, out);
}

// round 11
// speedup vs baseline: 1.0135x; 1.0135x over previous
#include <cuda_runtime.h>
#include <math.h>

#define NQ   12
#define DIM  4096
#define NL   4
#define TPB  256

// SU(2)-compressed fused RZ*RY*RX gate per (layer, wire): row0 only,
// (u00r, u00i, u01r, u01i). Row1 = (-conj(u01), conj(u00)) derived in-kernel.
__device__ float4 g_U4[NL * NQ];

__global__ void precompute_gates(const float* __restrict__ qw) {
    int id = threadIdx.x;
    if (id >= NL * NQ) return;
    float a = qw[3 * id + 0];
    float b = qw[3 * id + 1];
    float g = qw[3 * id + 2];
    float cA = cosf(0.5f * a), sA = sinf(0.5f * a);
    float cB = cosf(0.5f * b), sB = sinf(0.5f * b);
    float cC = cosf(0.5f * g), sC = sinf(0.5f * g);
    float m00r =  cB * cA, m00i =  sB * sA;
    float m01r = -sB * cA, m01i = -cB * sA;
    // row0 of U = e^{-iC} * (RY*RX row0)
    float u00r = cC * m00r + sC * m00i, u00i = cC * m00i - sC * m00r;
    float u01r = cC * m01r + sC * m01i, u01i = cC * m01i - sC * m01r;
    g_U4[id] = make_float4(u00r, u00i, u01r, u01i);
}

// phys address (element index) of logical amp under layout "active = {8..11}"
__device__ __forceinline__ int physHIGH(int x) {
    return ((x & 0xFF) << 4) | (((x >> 8) ^ x) & 15);
}

__device__ __forceinline__ float2 cmul(float2 a, float2 b) {
    return make_float2(a.x * b.x - a.y * b.y, a.x * b.y + a.y * b.x);
}

// Apply fused SU(2) gate on register-slot bit bb; ua = (u00r,u00i,u01r,u01i).
// Row1 derived: u10 = (-u01r, u01i), u11 = (u00r, -u00i). Negations fold into
// FFMA operand modifiers (free).
#define APPLY_GATE(bb, ua) do {                                              \
    _Pragma("unroll")                                                        \
    for (int m = 0; m < 8; m++) {                                            \
        const int lowm = (1 << (bb)) - 1;                                    \
        const int i0 = ((m & ~lowm) << 1) | (m & lowm);                      \
        const int i1 = i0 | (1 << (bb));                                     \
        float2 v0 = r[i0], v1 = r[i1];                                       \
        float2 n0, n1;                                                       \
        n0.x =  ua.x*v0.x - ua.y*v0.y + ua.z*v1.x - ua.w*v1.y;               \
        n0.y =  ua.x*v0.y + ua.y*v0.x + ua.z*v1.y + ua.w*v1.x;               \
        n1.x = -ua.z*v0.x - ua.w*v0.y + ua.x*v1.x + ua.y*v1.y;               \
        n1.y = -ua.z*v0.y + ua.w*v0.x + ua.x*v1.y - ua.y*v1.x;               \
        r[i0] = n0; r[i1] = n1;                                              \
    }                                                                        \
} while (0)

__global__ __launch_bounds__(TPB, 4) void qsim(const float* __restrict__ x,
                                               const float* __restrict__ dw,
                                               const float* __restrict__ db,
                                               float* __restrict__ out) {
    __shared__ float2 s_psi[DIM];          // 32 KB state (swizzled layouts)
    __shared__ float4 s_U4[NL * NQ];       // SU(2)-compressed gates (768 B)
    __shared__ float  s_x[NQ];
    __shared__ float2 s_w[NQ][2];          // per-BIT-POSITION local 2-vectors (layer 0 folded)
    __shared__ float  s_scalar[2];
    __shared__ float  s_red[8 * NQ];
    __shared__ float  s_q[NQ];

    const int t = threadIdx.x;
    const int bidx = blockIdx.x;

    for (int i = t; i < NL * NQ; i += TPB) s_U4[i] = g_U4[i];
    if (t < NQ) s_x[t] = x[bidx * NQ + t];
    __syncthreads();

    if (t == 0) {
        float ss = 0.f, ma = 0.f;
        #pragma unroll
        for (int w = 0; w < NQ; w++) {
            float v = s_x[w];
            ss += v * v;
            ma = fmaxf(ma, fabsf(v));
        }
        float rr = rsqrtf(fmaxf(ss, 1e-12f));
        s_scalar[0] = rr;
        s_scalar[1] = ma * rr;
    }
    __syncthreads();
    if (t < NQ) {
        float rr = s_scalar[0], m = s_scalar[1];
        float ang = 3.14159265358979f * (s_x[t] * rr) / (m + 1e-8f);
        float c = cosf(0.5f * ang);
        float s = sinf(0.5f * ang);
        // fuse layer-0 gate for wire t into the local 2-vector
        float4 ua = s_U4[t];
        int p = 11 - t;                    // wire t lives at bit position 11-t
        // w0 = row0 . (c, s);  w1 = row1 . (c, s) with row1 = (-conj(u01), conj(u00))
        s_w[p][0] = make_float2( ua.x * c + ua.z * s,  ua.y * c + ua.w * s);
        s_w[p][1] = make_float2(-ua.z * c + ua.x * s,  ua.w * c - ua.y * s);
    }
    __syncthreads();

    float2 r[16];                          // 16 amps per thread (register tile)
    const int storeBase = (t << 4) | (t & 15);   // universal store: addr = storeBase ^ s

    // ---------- init in HIGH ownership: L = (s<<8)|t, amp = prod of w[bit]
    {
        float2 ct = s_w[0][t & 1];
        #pragma unroll
        for (int p = 1; p < 8; p++) ct = cmul(ct, s_w[p][(t >> p) & 1]);
        float2 m01[4], m23[4], ctm[4];
        #pragma unroll
        for (int a = 0; a < 4; a++) {
            m01[a] = cmul(s_w[8][a & 1],  s_w[9][(a >> 1) & 1]);
            m23[a] = cmul(s_w[10][a & 1], s_w[11][(a >> 1) & 1]);
        }
        #pragma unroll
        for (int a = 0; a < 4; a++) ctm[a] = cmul(ct, m01[a]);
        #pragma unroll
        for (int s = 0; s < 16; s++) r[s] = cmul(ctm[s & 3], m23[s >> 2]);
        #pragma unroll
        for (int s = 0; s < 16; s++) s_psi[storeBase ^ s] = r[s];
    }
    __syncthreads();

    #pragma unroll 1
    for (int layer = 1; layer < NL; layer++) {
        // ---------- pass MID: active positions {4..7}; load HIGH layout w/ CNOT perm folded
        {
            int T  = ((t & 0xF0) << 4) | (t & 15);
            int Xt = T ^ (T >> 1) ^ ((t & 1) ? 0xC00 : 0);
            int base = physHIGH(Xt & 0xFFF);
            #pragma unroll
            for (int s = 0; s < 16; s++) {
                int Xs = ((s << 4) ^ (s << 3)) & 0xFFF;
                r[s] = s_psi[base ^ physHIGH(Xs)];
            }
        }
        {
            const float4 a4 = s_U4[layer * NQ + 7];
            APPLY_GATE(0, a4);   // position 4 = wire 7
            const float4 a5 = s_U4[layer * NQ + 6];
            APPLY_GATE(1, a5);   // position 5 = wire 6
            const float4 a6 = s_U4[layer * NQ + 5];
            APPLY_GATE(2, a6);   // position 6 = wire 5
            const float4 a7 = s_U4[layer * NQ + 4];
            APPLY_GATE(3, a7);   // position 7 = wire 4
        }
        __syncthreads();               // all loads done before stores clobber
        #pragma unroll
        for (int s = 0; s < 16; s++) s_psi[storeBase ^ s] = r[s];
        __syncthreads();

        // ---------- pass LOW: active {0..3}; load from MID layout
        {
            int base = ((t & 0xF0) << 4) | (t & 15);
            #pragma unroll
            for (int s = 0; s < 16; s++) r[s] = s_psi[base ^ ((s << 4) | s)];
        }
        {
            const float4 a0 = s_U4[layer * NQ + 11];
            APPLY_GATE(0, a0);   // position 0 = wire 11
            const float4 a1 = s_U4[layer * NQ + 10];
            APPLY_GATE(1, a1);
            const float4 a2 = s_U4[layer * NQ + 9];
            APPLY_GATE(2, a2);
            const float4 a3 = s_U4[layer * NQ + 8];
            APPLY_GATE(3, a3);
        }
        __syncthreads();
        #pragma unroll
        for (int s = 0; s < 16; s++) s_psi[storeBase ^ s] = r[s];
        __syncthreads();

        // ---------- pass HIGH: active {8..11}; load from LOW layout
        {
            int base = t ^ ((t >> 4) & 15);
            #pragma unroll
            for (int s = 0; s < 16; s++) r[s] = s_psi[base ^ (s << 8)];
        }
        {
            const float4 a8 = s_U4[layer * NQ + 3];
            APPLY_GATE(0, a8);   // position 8 = wire 3
            const float4 a9 = s_U4[layer * NQ + 2];
            APPLY_GATE(1, a9);
            const float4 a10 = s_U4[layer * NQ + 1];
            APPLY_GATE(2, a10);
            const float4 a11 = s_U4[layer * NQ + 0];
            APPLY_GATE(3, a11);
        }
        if (layer < NL - 1) {
            __syncthreads();
            #pragma unroll
            for (int s = 0; s < 16; s++) s_psi[storeBase ^ s] = r[s];
            __syncthreads();
        }
        // layer-boundary CNOT ring folds into next MID load / epilogue index map
    }

    // ---------- epilogue: Walsh-transform form of the signed probability sums.
    // r holds HIGH ownership: pre-final-ring logical L = (s<<8) | t.
    // masks: p=11 -> 7, p=10 -> 12, p=9 -> 14, p<=8 -> 15.
    float pr[16];
    #pragma unroll
    for (int s = 0; s < 16; s++) {
        float2 v = r[s];
        pr[s] = v.x * v.x + v.y * v.y;
    }
    float P[8], M[8];
    #pragma unroll
    for (int u = 0; u < 8; u++) {
        P[u] = pr[2 * u] + pr[2 * u + 1];
        M[u] = pr[2 * u] - pr[2 * u + 1];
    }
    float W15 = 0.f, W14 = 0.f, W12 = 0.f, W7 = 0.f;
    #pragma unroll
    for (int u = 0; u < 8; u++) {
        if (__popc(u) & 1)        { W15 -= M[u]; W14 -= P[u]; }
        else                      { W15 += M[u]; W14 += P[u]; }
        if (__popc(u >> 1) & 1)   W12 -= P[u]; else W12 += P[u];
        if (__popc(u & 3) & 1)    W7  -= M[u]; else W7  += M[u];
    }

    int xt = t ^ ((__popc(t) & 1) ? 0xC00 : 0);
    xt ^= xt >> 1; xt ^= xt >> 2; xt ^= xt >> 4; xt ^= xt >> 8;

    float z[NQ];
    #pragma unroll
    for (int w = 0; w < NQ; w++) {
        const int p = 11 - w;
        float Wv = (p == 11) ? W7 : (p == 10) ? W12 : (p == 9) ? W14 : W15;
        z[w] = ((xt >> p) & 1) ? -Wv : Wv;
    }

    const int lane = t & 31, warp = t >> 5;
    #pragma unroll
    for (int w = 0; w < NQ; w++) {
        float v = z[w];
        #pragma unroll
        for (int off = 16; off; off >>= 1)
            v += __shfl_down_sync(0xffffffffu, v, off);
        if (lane == 0) s_red[warp * NQ + w] = v;
    }
    __syncthreads();
    if (t < NQ) {
        float qv = 0.f;
        #pragma unroll
        for (int wp = 0; wp < 8; wp++) qv += s_red[wp * NQ + t];
        s_q[t] = qv;
    }
    __syncthreads();
    if (t < NQ) {
        float acc = db[t];
        #pragma unroll
        for (int w = 0; w < NQ; w++) acc += s_q[w] * dw[w * NQ + t];
        out[bidx * NQ + t] = tanhf(acc);
    }
}

extern "C" void kernel_launch(void* const* d_in, const int* in_sizes, int n_in,
                              void* d_out, int out_size) {
    const float* x  = (const float*)d_in[0];
    const float* qw = (const float*)d_in[1];
    const float* dw = (const float*)d_in[2];
    const float* db = (const float*)d_in[3];
    float* out = (float*)d_out;

    int batch = in_sizes[0] / NQ;

    precompute_gates<<<1, 64>>>(qw);
    qsim<<<batch, TPB>>>(x, dw, db, out);
}

// round 13
// speedup vs baseline: 1.0780x; 1.0636x over previous
#include <cuda_runtime.h>
#include <math.h>

#define NQ   12
#define DIM  4096
#define NL   4
#define TPB  256

// Phase-normalized fused RZ*RY*RX gate per (layer, wire): M = phi*U with
// phi = conj(u00)/|u00|, U in SU(2). Then:
//   row0 = ( c, b )            c = |u00| REAL, b = phi*u01 complex
//   row1 = ( e, d )            e = -phi^2*conj(b), d = phi^2*c  (complex)
// Product of per-gate phases is one global phase on the state ->
// probabilities (the only observable here) are EXACT.
// Storage: U0 = (c, br, bi, 0) ; U1 = (er, ei, dr, di)
__device__ float4 g_U0[NL * NQ];
__device__ float4 g_U1[NL * NQ];

__global__ void precompute_gates(const float* __restrict__ qw) {
    int id = threadIdx.x;
    if (id >= NL * NQ) return;
    float a = qw[3 * id + 0];
    float b = qw[3 * id + 1];
    float g = qw[3 * id + 2];
    float cA = cosf(0.5f * a), sA = sinf(0.5f * a);
    float cB = cosf(0.5f * b), sB = sinf(0.5f * b);
    float cC = cosf(0.5f * g), sC = sinf(0.5f * g);
    float m00r =  cB * cA, m00i =  sB * sA;
    float m01r = -sB * cA, m01i = -cB * sA;
    // row0 of U = e^{-iC} * (RY*RX row0)
    float u00r = cC * m00r + sC * m00i, u00i = cC * m00i - sC * m00r;
    float u01r = cC * m01r + sC * m01i, u01i = cC * m01i - sC * m01r;
    // phi = conj(u00)/|u00|
    float mag2 = u00r * u00r + u00i * u00i;
    float inv  = rsqrtf(fmaxf(mag2, 1e-24f));      // |u00| ~ 1 for this dataset
    float c  = mag2 * inv;                          // |u00|
    // b = phi * u01
    float br = (u01r * u00r + u01i * u00i) * inv;
    float bi = (u01i * u00r - u01r * u00i) * inv;
    // gphase = phi^2 = conj(u00)^2 / |u00|^2
    float gr = (u00r * u00r - u00i * u00i) / fmaxf(mag2, 1e-24f);
    float gi = (-2.f * u00r * u00i) / fmaxf(mag2, 1e-24f);
    // e = -gphase * conj(b);  d = gphase * c
    float er = -(gr * br + gi * bi);
    float ei = -(gi * br - gr * bi);
    float dr = gr * c;
    float di = gi * c;
    g_U0[id] = make_float4(c, br, bi, 0.f);
    g_U1[id] = make_float4(er, ei, dr, di);
}

// phys address (element index) of logical amp under layout "active = {8..11}"
__device__ __forceinline__ int physHIGH(int x) {
    return ((x & 0xFF) << 4) | (((x >> 8) ^ x) & 15);
}

__device__ __forceinline__ float2 cmul(float2 a, float2 b) {
    return make_float2(a.x * b.x - a.y * b.y, a.x * b.y + a.y * b.x);
}

// Apply phase-normalized gate on register-slot bit bb.
// u0 = (c, br, bi, -), u1 = (er, ei, dr, di): 14 FFMA per pair (was 16).
//   n0 = c*v0 + b*v1          (c real)
//   n1 = e*v0 + d*v1          (complex)
#define APPLY_GATE(bb, u0, u1) do {                                          \
    _Pragma("unroll")                                                        \
    for (int m = 0; m < 8; m++) {                                            \
        const int lowm = (1 << (bb)) - 1;                                    \
        const int i0 = ((m & ~lowm) << 1) | (m & lowm);                      \
        const int i1 = i0 | (1 << (bb));                                     \
        float2 v0 = r[i0], v1 = r[i1];                                       \
        float2 n0, n1;                                                       \
        n0.x = u0.x*v0.x + u0.y*v1.x - u0.z*v1.y;                            \
        n0.y = u0.x*v0.y + u0.y*v1.y + u0.z*v1.x;                            \
        n1.x = u1.x*v0.x - u1.y*v0.y + u1.z*v1.x - u1.w*v1.y;                \
        n1.y = u1.x*v0.y + u1.y*v0.x + u1.z*v1.y + u1.w*v1.x;                \
        r[i0] = n0; r[i1] = n1;                                              \
    }                                                                        \
} while (0)

__global__ __launch_bounds__(TPB, 3) void qsim(const float* __restrict__ x,
                                               const float* __restrict__ dw,
                                               const float* __restrict__ db,
                                               float* __restrict__ out) {
    __shared__ float2 s_psi[DIM];          // 32 KB state (swizzled layouts)
    __shared__ float4 s_U0[NL * NQ];       // row0 coefficients
    __shared__ float4 s_U1[NL * NQ];       // row1 coefficients
    __shared__ float  s_x[NQ];
    __shared__ float2 s_w[NQ][2];          // per-BIT-POSITION local 2-vectors (layer 0 folded)
    __shared__ float  s_scalar[2];
    __shared__ float  s_red[8 * NQ];
    __shared__ float  s_q[NQ];

    const int t = threadIdx.x;
    const int bidx = blockIdx.x;

    for (int i = t; i < NL * NQ; i += TPB) { s_U0[i] = g_U0[i]; s_U1[i] = g_U1[i]; }
    if (t < NQ) s_x[t] = x[bidx * NQ + t];
    __syncthreads();

    if (t == 0) {
        float ss = 0.f, ma = 0.f;
        #pragma unroll
        for (int w = 0; w < NQ; w++) {
            float v = s_x[w];
            ss += v * v;
            ma = fmaxf(ma, fabsf(v));
        }
        float rr = rsqrtf(fmaxf(ss, 1e-12f));
        s_scalar[0] = rr;
        s_scalar[1] = ma * rr;
    }
    __syncthreads();
    if (t < NQ) {
        float rr = s_scalar[0], m = s_scalar[1];
        float ang = 3.14159265358979f * (s_x[t] * rr) / (m + 1e-8f);
        float c = cosf(0.5f * ang);
        float s = sinf(0.5f * ang);
        // fuse layer-0 (phase-normalized) gate for wire t into the local 2-vector
        float4 u0 = s_U0[t];
        float4 u1 = s_U1[t];
        int p = 11 - t;                    // wire t lives at bit position 11-t
        // w0 = row0 . (c, s) ; w1 = row1 . (c, s)
        s_w[p][0] = make_float2(u0.x * c + u0.y * s, u0.z * s);
        s_w[p][1] = make_float2(u1.x * c + u1.z * s, u1.y * c + u1.w * s);
    }
    __syncthreads();

    float2 r[16];                          // 16 amps per thread (register tile)
    const int storeBase = (t << 4) | (t & 15);   // universal store: addr = storeBase ^ s

    // ---------- init in HIGH ownership: L = (s<<8)|t, amp = prod of w[bit]
    {
        float2 ct = s_w[0][t & 1];
        #pragma unroll
        for (int p = 1; p < 8; p++) ct = cmul(ct, s_w[p][(t >> p) & 1]);
        float2 m01[4], m23[4], ctm[4];
        #pragma unroll
        for (int a = 0; a < 4; a++) {
            m01[a] = cmul(s_w[8][a & 1],  s_w[9][(a >> 1) & 1]);
            m23[a] = cmul(s_w[10][a & 1], s_w[11][(a >> 1) & 1]);
        }
        #pragma unroll
        for (int a = 0; a < 4; a++) ctm[a] = cmul(ct, m01[a]);
        #pragma unroll
        for (int s = 0; s < 16; s++) r[s] = cmul(ctm[s & 3], m23[s >> 2]);
        #pragma unroll
        for (int s = 0; s < 16; s++) s_psi[storeBase ^ s] = r[s];
    }
    __syncthreads();

    #pragma unroll 1
    for (int layer = 1; layer < NL; layer++) {
        // ---------- pass MID: active positions {4..7}; load HIGH layout w/ CNOT perm folded
        {
            int T  = ((t & 0xF0) << 4) | (t & 15);
            int Xt = T ^ (T >> 1) ^ ((t & 1) ? 0xC00 : 0);
            int base = physHIGH(Xt & 0xFFF);
            #pragma unroll
            for (int s = 0; s < 16; s++) {
                int Xs = ((s << 4) ^ (s << 3)) & 0xFFF;
                r[s] = s_psi[base ^ physHIGH(Xs)];
            }
        }
        {
            const float4 p40 = s_U0[layer * NQ + 7], p41 = s_U1[layer * NQ + 7];
            APPLY_GATE(0, p40, p41);   // position 4 = wire 7
            const float4 p50 = s_U0[layer * NQ + 6], p51 = s_U1[layer * NQ + 6];
            APPLY_GATE(1, p50, p51);   // position 5 = wire 6
            const float4 p60 = s_U0[layer * NQ + 5], p61 = s_U1[layer * NQ + 5];
            APPLY_GATE(2, p60, p61);   // position 6 = wire 5
            const float4 p70 = s_U0[layer * NQ + 4], p71 = s_U1[layer * NQ + 4];
            APPLY_GATE(3, p70, p71);   // position 7 = wire 4
        }
        __syncthreads();               // all loads done before stores clobber
        #pragma unroll
        for (int s = 0; s < 16; s++) s_psi[storeBase ^ s] = r[s];
        __syncthreads();

        // ---------- pass LOW: active {0..3}; load from MID layout
        {
            int base = ((t & 0xF0) << 4) | (t & 15);
            #pragma unroll
            for (int s = 0; s < 16; s++) r[s] = s_psi[base ^ ((s << 4) | s)];
        }
        {
            const float4 p00 = s_U0[layer * NQ + 11], p01 = s_U1[layer * NQ + 11];
            APPLY_GATE(0, p00, p01);   // position 0 = wire 11
            const float4 p10 = s_U0[layer * NQ + 10], p11 = s_U1[layer * NQ + 10];
            APPLY_GATE(1, p10, p11);
            const float4 p20 = s_U0[layer * NQ + 9], p21 = s_U1[layer * NQ + 9];
            APPLY_GATE(2, p20, p21);
            const float4 p30 = s_U0[layer * NQ + 8], p31 = s_U1[layer * NQ + 8];
            APPLY_GATE(3, p30, p31);
        }
        __syncthreads();
        #pragma unroll
        for (int s = 0; s < 16; s++) s_psi[storeBase ^ s] = r[s];
        __syncthreads();

        // ---------- pass HIGH: active {8..11}; load from LOW layout
        {
            int base = t ^ ((t >> 4) & 15);
            #pragma unroll
            for (int s = 0; s < 16; s++) r[s] = s_psi[base ^ (s << 8)];
        }
        {
            const float4 p80 = s_U0[layer * NQ + 3], p81 = s_U1[layer * NQ + 3];
            APPLY_GATE(0, p80, p81);   // position 8 = wire 3
            const float4 p90 = s_U0[layer * NQ + 2], p91 = s_U1[layer * NQ + 2];
            APPLY_GATE(1, p90, p91);
            const float4 pa0 = s_U0[layer * NQ + 1], pa1 = s_U1[layer * NQ + 1];
            APPLY_GATE(2, pa0, pa1);
            const float4 pb0 = s_U0[layer * NQ + 0], pb1 = s_U1[layer * NQ + 0];
            APPLY_GATE(3, pb0, pb1);
        }
        if (layer < NL - 1) {
            __syncthreads();
            #pragma unroll
            for (int s = 0; s < 16; s++) s_psi[storeBase ^ s] = r[s];
            __syncthreads();
        }
        // layer-boundary CNOT ring folds into next MID load / epilogue index map
    }

    // ---------- epilogue: Walsh-transform form of the signed probability sums.
    // r holds HIGH ownership: pre-final-ring logical L = (s<<8) | t.
    // masks: p=11 -> 7, p=10 -> 12, p=9 -> 14, p<=8 -> 15.
    float pr[16];
    #pragma unroll
    for (int s = 0; s < 16; s++) {
        float2 v = r[s];
        pr[s] = v.x * v.x + v.y * v.y;
    }
    float P[8], M[8];
    #pragma unroll
    for (int u = 0; u < 8; u++) {
        P[u] = pr[2 * u] + pr[2 * u + 1];
        M[u] = pr[2 * u] - pr[2 * u + 1];
    }
    float W15 = 0.f, W14 = 0.f, W12 = 0.f, W7 = 0.f;
    #pragma unroll
    for (int u = 0; u < 8; u++) {
        if (__popc(u) & 1)        { W15 -= M[u]; W14 -= P[u]; }
        else                      { W15 += M[u]; W14 += P[u]; }
        if (__popc(u >> 1) & 1)   W12 -= P[u]; else W12 += P[u];
        if (__popc(u & 3) & 1)    W7  -= M[u]; else W7  += M[u];
    }

    int xt = t ^ ((__popc(t) & 1) ? 0xC00 : 0);
    xt ^= xt >> 1; xt ^= xt >> 2; xt ^= xt >> 4; xt ^= xt >> 8;

    float z[NQ];
    #pragma unroll
    for (int w = 0; w < NQ; w++) {
        const int p = 11 - w;
        float Wv = (p == 11) ? W7 : (p == 10) ? W12 : (p == 9) ? W14 : W15;
        z[w] = ((xt >> p) & 1) ? -Wv : Wv;
    }

    const int lane = t & 31, warp = t >> 5;
    #pragma unroll
    for (int w = 0; w < NQ; w++) {
        float v = z[w];
        #pragma unroll
        for (int off = 16; off; off >>= 1)
            v += __shfl_down_sync(0xffffffffu, v, off);
        if (lane == 0) s_red[warp * NQ + w] = v;
    }
    __syncthreads();
    if (t < NQ) {
        float qv = 0.f;
        #pragma unroll
        for (int wp = 0; wp < 8; wp++) qv += s_red[wp * NQ + t];
        s_q[t] = qv;
    }
    __syncthreads();
    if (t < NQ) {
        float acc = db[t];
        #pragma unroll
        for (int w = 0; w < NQ; w++) acc += s_q[w] * dw[w * NQ + t];
        out[bidx * NQ + t] = tanhf(acc);
    }
}

extern "C" void kernel_launch(void* const* d_in, const int* in_sizes, int n_in,
                              void* d_out, int out_size) {
    const float* x  = (const float*)d_in[0];
    const float* qw = (const float*)d_in[1];
    const float* dw = (const float*)d_in[2];
    const float* db = (const float*)d_in[3];
    float* out = (float*)d_out;

    int batch = in_sizes[0] / NQ;

    precompute_gates<<<1, 64>>>(qw);
    qsim<<<batch, TPB>>>(x, dw, db, out);
}

// round 14
// speedup vs baseline: 1.1747x; 1.0897x over previous
#include <cuda_runtime.h>
#include <math.h>

#define NQ   12
#define DIM  4096
#define NL   4
#define TPB  256

__device__ __forceinline__ float2 cmul(float2 a, float2 b) {
    return make_float2(a.x * b.x - a.y * b.y, a.x * b.y + a.y * b.x);
}

// Phase-normalized fused RZ*RY*RX gate per (layer, wire): M = phi*U,
// phi = conj(u00)/|u00|, U in SU(2). Decomposition:
//   M = diag(1, phi^2) * M''     with  M'' = [[c, b], [-conj(b), c]], c real.
// 12-FFMA form applies M''; the deferred diag(1, phi^2) factors commute with
// other wires' gates and are either (a) folded into the gate (14-FFMA form,
// HIGH passes of layers 1-2), (b) accumulated into a per-thread complex
// lo_n[t] applied once at layer end (MID/LOW wires, layers 1-2), or
// (c) dropped (layer 3: only ring perm + |.|^2 follow; phases are dead).
// Storage: U0 = (c, br, bi, 0) ; U1 = (er, ei, dr, di) with
//   e = -phi^2*conj(b), d = phi^2*c   (row1 of the 14-FFMA form M)
__device__ float4 g_U0[NL * NQ];
__device__ float4 g_U1[NL * NQ];
__device__ float2 g_lo[2 * 256];   // lo_n[t] for layers 1,2 (deferred MID/LOW diagonals)

__global__ void precompute_gates(const float* __restrict__ qw) {
    __shared__ float2 s_phi2[NL * NQ];
    int id = threadIdx.x;
    if (id < NL * NQ) {
        float a = qw[3 * id + 0];
        float b = qw[3 * id + 1];
        float g = qw[3 * id + 2];
        float cA = cosf(0.5f * a), sA = sinf(0.5f * a);
        float cB = cosf(0.5f * b), sB = sinf(0.5f * b);
        float cC = cosf(0.5f * g), sC = sinf(0.5f * g);
        float m00r =  cB * cA, m00i =  sB * sA;
        float m01r = -sB * cA, m01i = -cB * sA;
        // row0 of U = e^{-iC} * (RY*RX row0)
        float u00r = cC * m00r + sC * m00i, u00i = cC * m00i - sC * m00r;
        float u01r = cC * m01r + sC * m01i, u01i = cC * m01i - sC * m01r;
        float mag2 = u00r * u00r + u00i * u00i;
        float inv  = rsqrtf(fmaxf(mag2, 1e-24f));
        float c  = mag2 * inv;                          // |u00|
        float br = (u01r * u00r + u01i * u00i) * inv;   // b = phi*u01
        float bi = (u01i * u00r - u01r * u00i) * inv;
        float gr = (u00r * u00r - u00i * u00i) / fmaxf(mag2, 1e-24f);  // phi^2
        float gi = (-2.f * u00r * u00i) / fmaxf(mag2, 1e-24f);
        float er = -(gr * br + gi * bi);
        float ei = -(gi * br - gr * bi);
        float dr = gr * c;
        float di = gi * c;
        g_U0[id] = make_float4(c, br, bi, 0.f);
        g_U1[id] = make_float4(er, ei, dr, di);
        s_phi2[id] = make_float2(gr, gi);
    }
    __syncthreads();
    // lo_n[t] = prod over set bits p (0..7) of t of phi^2 of (layer n, wire 11-p)
    int t = threadIdx.x;  // 0..255
    #pragma unroll
    for (int n = 1; n <= 2; n++) {
        float2 lo = make_float2(1.f, 0.f);
        #pragma unroll
        for (int p = 0; p < 8; p++)
            if ((t >> p) & 1) lo = cmul(lo, s_phi2[n * NQ + (11 - p)]);
        g_lo[(n - 1) * 256 + t] = lo;
    }
}

// phys address (element index) of logical amp under layout "active = {8..11}"
__device__ __forceinline__ int physHIGH(int x) {
    return ((x & 0xFF) << 4) | (((x >> 8) ^ x) & 15);
}

// 12-FFMA gate: M'' = [[c, b], [-conj(b), c]], u0 = (c, br, bi, -)
#define APPLY_G12(bb, u0) do {                                               \
    _Pragma("unroll")                                                        \
    for (int m = 0; m < 8; m++) {                                            \
        const int lowm = (1 << (bb)) - 1;                                    \
        const int i0 = ((m & ~lowm) << 1) | (m & lowm);                      \
        const int i1 = i0 | (1 << (bb));                                     \
        float2 v0 = r[i0], v1 = r[i1];                                       \
        float2 n0, n1;                                                       \
        n0.x = u0.x*v0.x + u0.y*v1.x - u0.z*v1.y;                            \
        n0.y = u0.x*v0.y + u0.y*v1.y + u0.z*v1.x;                            \
        n1.x = u0.x*v1.x - u0.y*v0.x - u0.z*v0.y;                            \
        n1.y = u0.x*v1.y - u0.y*v0.y + u0.z*v0.x;                            \
        r[i0] = n0; r[i1] = n1;                                              \
    }                                                                        \
} while (0)

// 14-FFMA gate (diagonal folded): u0 = (c, br, bi, -), u1 = (er, ei, dr, di)
#define APPLY_G14(bb, u0, u1) do {                                           \
    _Pragma("unroll")                                                        \
    for (int m = 0; m < 8; m++) {                                            \
        const int lowm = (1 << (bb)) - 1;                                    \
        const int i0 = ((m & ~lowm) << 1) | (m & lowm);                      \
        const int i1 = i0 | (1 << (bb));                                     \
        float2 v0 = r[i0], v1 = r[i1];                                       \
        float2 n0, n1;                                                       \
        n0.x = u0.x*v0.x + u0.y*v1.x - u0.z*v1.y;                            \
        n0.y = u0.x*v0.y + u0.y*v1.y + u0.z*v1.x;                            \
        n1.x = u1.x*v0.x - u1.y*v0.y + u1.z*v1.x - u1.w*v1.y;                \
        n1.y = u1.x*v0.y + u1.y*v0.x + u1.z*v1.y + u1.w*v1.x;                \
        r[i0] = n0; r[i1] = n1;                                              \
    }                                                                        \
} while (0)

__global__ __launch_bounds__(TPB, 3) void qsim(const float* __restrict__ x,
                                               const float* __restrict__ dw,
                                               const float* __restrict__ db,
                                               float* __restrict__ out) {
    __shared__ float2 s_psi[DIM];          // 32 KB state (swizzled layouts)
    __shared__ float4 s_U0[NL * NQ];       // row0 coefficients (c, br, bi)
    __shared__ float4 s_U1[NL * NQ];       // row1 coefficients (14-form)
    __shared__ float2 s_lo[2 * 256];       // deferred-diagonal tables, layers 1,2
    __shared__ float  s_x[NQ];
    __shared__ float2 s_w[NQ][2];          // per-BIT-POSITION local 2-vectors (layer 0 folded)
    __shared__ float  s_scalar[2];
    __shared__ float  s_red[8 * NQ];
    __shared__ float  s_q[NQ];

    const int t = threadIdx.x;
    const int bidx = blockIdx.x;

    for (int i = t; i < NL * NQ; i += TPB) { s_U0[i] = g_U0[i]; s_U1[i] = g_U1[i]; }
    #pragma unroll
    for (int i = 0; i < 2; i++) s_lo[i * 256 + t] = g_lo[i * 256 + t];
    if (t < NQ) s_x[t] = x[bidx * NQ + t];
    __syncthreads();

    if (t == 0) {
        float ss = 0.f, ma = 0.f;
        #pragma unroll
        for (int w = 0; w < NQ; w++) {
            float v = s_x[w];
            ss += v * v;
            ma = fmaxf(ma, fabsf(v));
        }
        float rr = rsqrtf(fmaxf(ss, 1e-12f));
        s_scalar[0] = rr;
        s_scalar[1] = ma * rr;
    }
    __syncthreads();
    if (t < NQ) {
        float rr = s_scalar[0], m = s_scalar[1];
        float ang = 3.14159265358979f * (s_x[t] * rr) / (m + 1e-8f);
        float c = cosf(0.5f * ang);
        float s = sinf(0.5f * ang);
        // fuse layer-0 (phase-normalized, 14-form) gate for wire t into local 2-vector
        float4 u0 = s_U0[t];
        float4 u1 = s_U1[t];
        int p = 11 - t;                    // wire t lives at bit position 11-t
        s_w[p][0] = make_float2(u0.x * c + u0.y * s, u0.z * s);
        s_w[p][1] = make_float2(u1.x * c + u1.z * s, u1.y * c + u1.w * s);
    }
    __syncthreads();

    float2 r[16];                          // 16 amps per thread (register tile)
    const int storeBase = (t << 4) | (t & 15);   // universal store: addr = storeBase ^ s

    // ---------- init in HIGH ownership: L = (s<<8)|t, amp = prod of w[bit]
    {
        float2 ct = s_w[0][t & 1];
        #pragma unroll
        for (int p = 1; p < 8; p++) ct = cmul(ct, s_w[p][(t >> p) & 1]);
        float2 m01[4], m23[4], ctm[4];
        #pragma unroll
        for (int a = 0; a < 4; a++) {
            m01[a] = cmul(s_w[8][a & 1],  s_w[9][(a >> 1) & 1]);
            m23[a] = cmul(s_w[10][a & 1], s_w[11][(a >> 1) & 1]);
        }
        #pragma unroll
        for (int a = 0; a < 4; a++) ctm[a] = cmul(ct, m01[a]);
        #pragma unroll
        for (int s = 0; s < 16; s++) r[s] = cmul(ctm[s & 3], m23[s >> 2]);
        #pragma unroll
        for (int s = 0; s < 16; s++) s_psi[storeBase ^ s] = r[s];
    }
    __syncthreads();

    #pragma unroll 1
    for (int layer = 1; layer < NL; layer++) {
        // ---------- pass MID: active positions {4..7}; load HIGH layout w/ CNOT perm folded
        // 12-form gates; diagonals deferred into lo (layers 1,2) or dropped (layer 3)
        {
            int T  = ((t & 0xF0) << 4) | (t & 15);
            int Xt = T ^ (T >> 1) ^ ((t & 1) ? 0xC00 : 0);
            int base = physHIGH(Xt & 0xFFF);
            #pragma unroll
            for (int s = 0; s < 16; s++) {
                int Xs = ((s << 4) ^ (s << 3)) & 0xFFF;
                r[s] = s_psi[base ^ physHIGH(Xs)];
            }
        }
        {
            const float4 p4 = s_U0[layer * NQ + 7];
            APPLY_G12(0, p4);   // position 4 = wire 7
            const float4 p5 = s_U0[layer * NQ + 6];
            APPLY_G12(1, p5);   // position 5 = wire 6
            const float4 p6 = s_U0[layer * NQ + 5];
            APPLY_G12(2, p6);   // position 6 = wire 5
            const float4 p7 = s_U0[layer * NQ + 4];
            APPLY_G12(3, p7);   // position 7 = wire 4
        }
        __syncthreads();               // all loads done before stores clobber
        #pragma unroll
        for (int s = 0; s < 16; s++) s_psi[storeBase ^ s] = r[s];
        __syncthreads();

        // ---------- pass LOW: active {0..3}; load from MID layout; 12-form gates
        {
            int base = ((t & 0xF0) << 4) | (t & 15);
            #pragma unroll
            for (int s = 0; s < 16; s++) r[s] = s_psi[base ^ ((s << 4) | s)];
        }
        {
            const float4 p0 = s_U0[layer * NQ + 11];
            APPLY_G12(0, p0);   // position 0 = wire 11
            const float4 p1 = s_U0[layer * NQ + 10];
            APPLY_G12(1, p1);
            const float4 p2 = s_U0[layer * NQ + 9];
            APPLY_G12(2, p2);
            const float4 p3 = s_U0[layer * NQ + 8];
            APPLY_G12(3, p3);
        }
        __syncthreads();
        #pragma unroll
        for (int s = 0; s < 16; s++) s_psi[storeBase ^ s] = r[s];
        __syncthreads();

        // ---------- pass HIGH: active {8..11}; load from LOW layout
        {
            int base = t ^ ((t >> 4) & 15);
            #pragma unroll
            for (int s = 0; s < 16; s++) r[s] = s_psi[base ^ (s << 8)];
        }
        if (layer < NL - 1) {
            // 14-form gates (own diagonal folded in)
            {
                const float4 p80 = s_U0[layer * NQ + 3], p81 = s_U1[layer * NQ + 3];
                APPLY_G14(0, p80, p81);   // position 8 = wire 3
                const float4 p90 = s_U0[layer * NQ + 2], p91 = s_U1[layer * NQ + 2];
                APPLY_G14(1, p90, p91);
                const float4 pa0 = s_U0[layer * NQ + 1], pa1 = s_U1[layer * NQ + 1];
                APPLY_G14(2, pa0, pa1);
                const float4 pb0 = s_U0[layer * NQ + 0], pb1 = s_U1[layer * NQ + 0];
                APPLY_G14(3, pb0, pb1);
            }
            // apply deferred MID/LOW diagonal for this layer: per-thread constant
            {
                float2 lo = s_lo[(layer - 1) * 256 + t];
                #pragma unroll
                for (int s = 0; s < 16; s++) r[s] = cmul(r[s], lo);
            }
            __syncthreads();
            #pragma unroll
            for (int s = 0; s < 16; s++) s_psi[storeBase ^ s] = r[s];
            __syncthreads();
        } else {
            // last layer: phases dead after |.|^2 -> 12-form, no lo, no store
            const float4 p8 = s_U0[layer * NQ + 3];
            APPLY_G12(0, p8);   // position 8 = wire 3
            const float4 p9 = s_U0[layer * NQ + 2];
            APPLY_G12(1, p9);
            const float4 pa = s_U0[layer * NQ + 1];
            APPLY_G12(2, pa);
            const float4 pb = s_U0[layer * NQ + 0];
            APPLY_G12(3, pb);
        }
        // layer-boundary CNOT ring folds into next MID load / epilogue index map
    }

    // ---------- epilogue: Walsh-transform form of the signed probability sums.
    // r holds HIGH ownership: pre-final-ring logical L = (s<<8) | t.
    // masks: p=11 -> 7, p=10 -> 12, p=9 -> 14, p<=8 -> 15.
    float pr[16];
    #pragma unroll
    for (int s = 0; s < 16; s++) {
        float2 v = r[s];
        pr[s] = v.x * v.x + v.y * v.y;
    }
    float P[8], M[8];
    #pragma unroll
    for (int u = 0; u < 8; u++) {
        P[u] = pr[2 * u] + pr[2 * u + 1];
        M[u] = pr[2 * u] - pr[2 * u + 1];
    }
    float W15 = 0.f, W14 = 0.f, W12 = 0.f, W7 = 0.f;
    #pragma unroll
    for (int u = 0; u < 8; u++) {
        if (__popc(u) & 1)        { W15 -= M[u]; W14 -= P[u]; }
        else                      { W15 += M[u]; W14 += P[u]; }
        if (__popc(u >> 1) & 1)   W12 -= P[u]; else W12 += P[u];
        if (__popc(u & 3) & 1)    W7  -= M[u]; else W7  += M[u];
    }

    int xt = t ^ ((__popc(t) & 1) ? 0xC00 : 0);
    xt ^= xt >> 1; xt ^= xt >> 2; xt ^= xt >> 4; xt ^= xt >> 8;

    float z[NQ];
    #pragma unroll
    for (int w = 0; w < NQ; w++) {
        const int p = 11 - w;
        float Wv = (p == 11) ? W7 : (p == 10) ? W12 : (p == 9) ? W14 : W15;
        z[w] = ((xt >> p) & 1) ? -Wv : Wv;
    }

    const int lane = t & 31, warp = t >> 5;
    #pragma unroll
    for (int w = 0; w < NQ; w++) {
        float v = z[w];
        #pragma unroll
        for (int off = 16; off; off >>= 1)
            v += __shfl_down_sync(0xffffffffu, v, off);
        if (lane == 0) s_red[warp * NQ + w] = v;
    }
    __syncthreads();
    if (t < NQ) {
        float qv = 0.f;
        #pragma unroll
        for (int wp = 0; wp < 8; wp++) qv += s_red[wp * NQ + t];
        s_q[t] = qv;
    }
    __syncthreads();
    if (t < NQ) {
        float acc = db[t];
        #pragma unroll
        for (int w = 0; w < NQ; w++) acc += s_q[w] * dw[w * NQ + t];
        out[bidx * NQ + t] = tanhf(acc);
    }
}

extern "C" void kernel_launch(void* const* d_in, const int* in_sizes, int n_in,
                              void* d_out, int out_size) {
    const float* x  = (const float*)d_in[0];
    const float* qw = (const float*)d_in[1];
    const float* dw = (const float*)d_in[2];
    const float* db = (const float*)d_in[3];
    float* out = (float*)d_out;

    int batch = in_sizes[0] / NQ;

    precompute_gates<<<1, 256>>>(qw);
    qsim<<<batch, TPB>>>(x, dw, db, out);
}

// round 15
// speedup vs baseline: 1.2056x; 1.0263x over previous
#include <cuda_runtime.h>
#include <math.h>

#define NQ   12
#define DIM  4096
#define NL   4
#define TPB  256

__device__ __forceinline__ float2 cmul(float2 a, float2 b) {
    return make_float2(a.x * b.x - a.y * b.y, a.x * b.y + a.y * b.x);
}

// Phase-normalized fused RZ*RY*RX gate per (layer, wire): M = phi*U,
// phi = conj(u00)/|u00|, U in SU(2). M = diag(1, phi^2) * M'' with
// M'' = [[c, b], [-conj(b), c]], c real (12-FFMA form). Deferred diagonals:
// folded into 14-form (HIGH gates, layers 1-2), accumulated into per-thread
// lo_n[t] (MID/LOW wires, layers 1-2) which is itself FOLDED into the
// position-8 HIGH gate (16-FFMA form), or dropped (layer 3: dead phases).
// Storage: U0 = (c, br, bi, 0) ; U1 = (er, ei, dr, di)
__device__ float4 g_U0[NL * NQ];
__device__ float4 g_U1[NL * NQ];
__device__ float2 g_lo[2 * 256];   // lo_n[t] for layers 1,2

__global__ void precompute_gates(const float* __restrict__ qw) {
    __shared__ float2 s_phi2[NL * NQ];
    int id = threadIdx.x;
    if (id < NL * NQ) {
        float a = qw[3 * id + 0];
        float b = qw[3 * id + 1];
        float g = qw[3 * id + 2];
        float cA = cosf(0.5f * a), sA = sinf(0.5f * a);
        float cB = cosf(0.5f * b), sB = sinf(0.5f * b);
        float cC = cosf(0.5f * g), sC = sinf(0.5f * g);
        float m00r =  cB * cA, m00i =  sB * sA;
        float m01r = -sB * cA, m01i = -cB * sA;
        float u00r = cC * m00r + sC * m00i, u00i = cC * m00i - sC * m00r;
        float u01r = cC * m01r + sC * m01i, u01i = cC * m01i - sC * m01r;
        float mag2 = u00r * u00r + u00i * u00i;
        float inv  = rsqrtf(fmaxf(mag2, 1e-24f));
        float c  = mag2 * inv;                          // |u00|
        float br = (u01r * u00r + u01i * u00i) * inv;   // b = phi*u01
        float bi = (u01i * u00r - u01r * u00i) * inv;
        float gr = (u00r * u00r - u00i * u00i) / fmaxf(mag2, 1e-24f);  // phi^2
        float gi = (-2.f * u00r * u00i) / fmaxf(mag2, 1e-24f);
        float er = -(gr * br + gi * bi);
        float ei = -(gi * br - gr * bi);
        float dr = gr * c;
        float di = gi * c;
        g_U0[id] = make_float4(c, br, bi, 0.f);
        g_U1[id] = make_float4(er, ei, dr, di);
        s_phi2[id] = make_float2(gr, gi);
    }
    __syncthreads();
    // lo_n[t] = prod over set bits p (0..7) of t of phi^2 of (layer n, wire 11-p)
    int t = threadIdx.x;  // 0..255
    #pragma unroll
    for (int n = 1; n <= 2; n++) {
        float2 lo = make_float2(1.f, 0.f);
        #pragma unroll
        for (int p = 0; p < 8; p++)
            if ((t >> p) & 1) lo = cmul(lo, s_phi2[n * NQ + (11 - p)]);
        g_lo[(n - 1) * 256 + t] = lo;
    }
}

// phys address (element index) of logical amp under layout "active = {8..11}"
__device__ __forceinline__ int physHIGH(int x) {
    return ((x & 0xFF) << 4) | (((x >> 8) ^ x) & 15);
}

// 12-FFMA gate: M'' = [[c, b], [-conj(b), c]], u0 = (c, br, bi, -)
#define APPLY_G12(bb, u0) do {                                               \
    _Pragma("unroll")                                                        \
    for (int m = 0; m < 8; m++) {                                            \
        const int lowm = (1 << (bb)) - 1;                                    \
        const int i0 = ((m & ~lowm) << 1) | (m & lowm);                      \
        const int i1 = i0 | (1 << (bb));                                     \
        float2 v0 = r[i0], v1 = r[i1];                                       \
        float2 n0, n1;                                                       \
        n0.x = u0.x*v0.x + u0.y*v1.x - u0.z*v1.y;                            \
        n0.y = u0.x*v0.y + u0.y*v1.y + u0.z*v1.x;                            \
        n1.x = u0.x*v1.x - u0.y*v0.x - u0.z*v0.y;                            \
        n1.y = u0.x*v1.y - u0.y*v0.y + u0.z*v0.x;                            \
        r[i0] = n0; r[i1] = n1;                                              \
    }                                                                        \
} while (0)

// 14-FFMA gate (diagonal folded): u0 = (c, br, bi, -), u1 = (er, ei, dr, di)
#define APPLY_G14(bb, u0, u1) do {                                           \
    _Pragma("unroll")                                                        \
    for (int m = 0; m < 8; m++) {                                            \
        const int lowm = (1 << (bb)) - 1;                                    \
        const int i0 = ((m & ~lowm) << 1) | (m & lowm);                      \
        const int i1 = i0 | (1 << (bb));                                     \
        float2 v0 = r[i0], v1 = r[i1];                                       \
        float2 n0, n1;                                                       \
        n0.x = u0.x*v0.x + u0.y*v1.x - u0.z*v1.y;                            \
        n0.y = u0.x*v0.y + u0.y*v1.y + u0.z*v1.x;                            \
        n1.x = u1.x*v0.x - u1.y*v0.y + u1.z*v1.x - u1.w*v1.y;                \
        n1.y = u1.x*v0.y + u1.y*v0.x + u1.z*v1.y + u1.w*v1.x;                \
        r[i0] = n0; r[i1] = n1;                                              \
    }                                                                        \
} while (0)

// 16-FFMA general gate: complex 2x2 rows (m00, m01) / (m10, m11)
#define APPLY_G16(bb, m00, m01, m10, m11) do {                               \
    _Pragma("unroll")                                                        \
    for (int m = 0; m < 8; m++) {                                            \
        const int lowm = (1 << (bb)) - 1;                                    \
        const int i0 = ((m & ~lowm) << 1) | (m & lowm);                      \
        const int i1 = i0 | (1 << (bb));                                     \
        float2 v0 = r[i0], v1 = r[i1];                                       \
        float2 n0, n1;                                                       \
        n0.x = m00.x*v0.x - m00.y*v0.y + m01.x*v1.x - m01.y*v1.y;            \
        n0.y = m00.x*v0.y + m00.y*v0.x + m01.x*v1.y + m01.y*v1.x;            \
        n1.x = m10.x*v0.x - m10.y*v0.y + m11.x*v1.x - m11.y*v1.y;            \
        n1.y = m10.x*v0.y + m10.y*v0.x + m11.x*v1.y + m11.y*v1.x;            \
        r[i0] = n0; r[i1] = n1;                                              \
    }                                                                        \
} while (0)

__global__ __launch_bounds__(TPB, 3) void qsim(const float* __restrict__ x,
                                               const float* __restrict__ dw,
                                               const float* __restrict__ db,
                                               float* __restrict__ out) {
    __shared__ float2 s_psi[DIM];          // 32 KB state (swizzled layouts)
    __shared__ float4 s_U0[NL * NQ];       // row0 coefficients (c, br, bi)
    __shared__ float4 s_U1[NL * NQ];       // row1 coefficients (14-form)
    __shared__ float2 s_lo[2 * 256];       // deferred-diagonal tables, layers 1,2
    __shared__ float  s_x[NQ];
    __shared__ float2 s_w[NQ][2];          // per-BIT-POSITION local 2-vectors (layer 0 folded)
    __shared__ float  s_scalar[2];
    __shared__ float  s_z[TPB * 13];       // per-thread z values (pad 13: conflict-free)
    __shared__ float  s_p[12 * 17];        // stage-B partials (12 wires x 16 groups, pad 17)
    __shared__ float  s_q[NQ];

    const int t = threadIdx.x;
    const int bidx = blockIdx.x;

    for (int i = t; i < NL * NQ; i += TPB) { s_U0[i] = g_U0[i]; s_U1[i] = g_U1[i]; }
    #pragma unroll
    for (int i = 0; i < 2; i++) s_lo[i * 256 + t] = g_lo[i * 256 + t];
    if (t < NQ) s_x[t] = x[bidx * NQ + t];
    __syncthreads();

    if (t == 0) {
        float ss = 0.f, ma = 0.f;
        #pragma unroll
        for (int w = 0; w < NQ; w++) {
            float v = s_x[w];
            ss += v * v;
            ma = fmaxf(ma, fabsf(v));
        }
        float rr = rsqrtf(fmaxf(ss, 1e-12f));
        s_scalar[0] = rr;
        s_scalar[1] = ma * rr;
    }
    __syncthreads();
    if (t < NQ) {
        float rr = s_scalar[0], m = s_scalar[1];
        float ang = 3.14159265358979f * (s_x[t] * rr) / (m + 1e-8f);
        float c = cosf(0.5f * ang);
        float s = sinf(0.5f * ang);
        // fuse layer-0 (phase-normalized, 14-form) gate for wire t into local 2-vector
        float4 u0 = s_U0[t];
        float4 u1 = s_U1[t];
        int p = 11 - t;                    // wire t lives at bit position 11-t
        s_w[p][0] = make_float2(u0.x * c + u0.y * s, u0.z * s);
        s_w[p][1] = make_float2(u1.x * c + u1.z * s, u1.y * c + u1.w * s);
    }
    __syncthreads();

    float2 r[16];                          // 16 amps per thread (register tile)
    const int storeBase = (t << 4) | (t & 15);   // universal store: addr = storeBase ^ s

    // ---------- init in HIGH ownership: L = (s<<8)|t, amp = prod of w[bit]
    {
        float2 ct = s_w[0][t & 1];
        #pragma unroll
        for (int p = 1; p < 8; p++) ct = cmul(ct, s_w[p][(t >> p) & 1]);
        float2 m01[4], m23[4], ctm[4];
        #pragma unroll
        for (int a = 0; a < 4; a++) {
            m01[a] = cmul(s_w[8][a & 1],  s_w[9][(a >> 1) & 1]);
            m23[a] = cmul(s_w[10][a & 1], s_w[11][(a >> 1) & 1]);
        }
        #pragma unroll
        for (int a = 0; a < 4; a++) ctm[a] = cmul(ct, m01[a]);
        #pragma unroll
        for (int s = 0; s < 16; s++) r[s] = cmul(ctm[s & 3], m23[s >> 2]);
        #pragma unroll
        for (int s = 0; s < 16; s++) s_psi[storeBase ^ s] = r[s];
    }
    __syncthreads();

    #pragma unroll 1
    for (int layer = 1; layer < NL; layer++) {
        // ---------- pass MID: active positions {4..7}; load HIGH layout w/ CNOT perm folded
        {
            int T  = ((t & 0xF0) << 4) | (t & 15);
            int Xt = T ^ (T >> 1) ^ ((t & 1) ? 0xC00 : 0);
            int base = physHIGH(Xt & 0xFFF);
            #pragma unroll
            for (int s = 0; s < 16; s++) {
                int Xs = ((s << 4) ^ (s << 3)) & 0xFFF;
                r[s] = s_psi[base ^ physHIGH(Xs)];
            }
        }
        {
            const float4 p4 = s_U0[layer * NQ + 7];
            APPLY_G12(0, p4);   // position 4 = wire 7
            const float4 p5 = s_U0[layer * NQ + 6];
            APPLY_G12(1, p5);   // position 5 = wire 6
            const float4 p6 = s_U0[layer * NQ + 5];
            APPLY_G12(2, p6);   // position 6 = wire 5
            const float4 p7 = s_U0[layer * NQ + 4];
            APPLY_G12(3, p7);   // position 7 = wire 4
        }
        __syncthreads();               // all loads done before stores clobber
        #pragma unroll
        for (int s = 0; s < 16; s++) s_psi[storeBase ^ s] = r[s];
        __syncthreads();

        // ---------- pass LOW: active {0..3}; load from MID layout; 12-form gates
        {
            int base = ((t & 0xF0) << 4) | (t & 15);
            #pragma unroll
            for (int s = 0; s < 16; s++) r[s] = s_psi[base ^ ((s << 4) | s)];
        }
        {
            const float4 p0 = s_U0[layer * NQ + 11];
            APPLY_G12(0, p0);   // position 0 = wire 11
            const float4 p1 = s_U0[layer * NQ + 10];
            APPLY_G12(1, p1);
            const float4 p2 = s_U0[layer * NQ + 9];
            APPLY_G12(2, p2);
            const float4 p3 = s_U0[layer * NQ + 8];
            APPLY_G12(3, p3);
        }
        __syncthreads();
        #pragma unroll
        for (int s = 0; s < 16; s++) s_psi[storeBase ^ s] = r[s];
        __syncthreads();

        // ---------- pass HIGH: active {8..11}; load from LOW layout
        {
            int base = t ^ ((t >> 4) & 15);
            #pragma unroll
            for (int s = 0; s < 16; s++) r[s] = s_psi[base ^ (s << 8)];
        }
        if (layer < NL - 1) {
            // position-8 gate: 16-form with the deferred MID/LOW diagonal (lo)
            // premultiplied into its coefficients (scalar commutes with layer gates)
            {
                float2 lo = s_lo[(layer - 1) * 256 + t];
                float4 u0 = s_U0[layer * NQ + 3];
                float4 u1 = s_U1[layer * NQ + 3];
                float2 m00 = make_float2(lo.x * u0.x, lo.y * u0.x);      // lo * c (c real)
                float2 m01 = cmul(lo, make_float2(u0.y, u0.z));          // lo * b
                float2 m10 = cmul(lo, make_float2(u1.x, u1.y));          // lo * e
                float2 m11 = cmul(lo, make_float2(u1.z, u1.w));          // lo * d
                APPLY_G16(0, m00, m01, m10, m11);   // position 8 = wire 3
            }
            {
                const float4 p90 = s_U0[layer * NQ + 2], p91 = s_U1[layer * NQ + 2];
                APPLY_G14(1, p90, p91);
                const float4 pa0 = s_U0[layer * NQ + 1], pa1 = s_U1[layer * NQ + 1];
                APPLY_G14(2, pa0, pa1);
                const float4 pb0 = s_U0[layer * NQ + 0], pb1 = s_U1[layer * NQ + 0];
                APPLY_G14(3, pb0, pb1);
            }
            __syncthreads();
            #pragma unroll
            for (int s = 0; s < 16; s++) s_psi[storeBase ^ s] = r[s];
            __syncthreads();
        } else {
            // last layer: phases dead after |.|^2 -> 12-form, no lo, no store
            const float4 p8 = s_U0[layer * NQ + 3];
            APPLY_G12(0, p8);   // position 8 = wire 3
            const float4 p9 = s_U0[layer * NQ + 2];
            APPLY_G12(1, p9);
            const float4 pa = s_U0[layer * NQ + 1];
            APPLY_G12(2, pa);
            const float4 pb = s_U0[layer * NQ + 0];
            APPLY_G12(3, pb);
        }
        // layer-boundary CNOT ring folds into next MID load / epilogue index map
    }

    // ---------- epilogue: Walsh-transform form of the signed probability sums.
    // r holds HIGH ownership: pre-final-ring logical L = (s<<8) | t.
    // masks: p=11 -> 7, p=10 -> 12, p=9 -> 14, p<=8 -> 15.
    float pr[16];
    #pragma unroll
    for (int s = 0; s < 16; s++) {
        float2 v = r[s];
        pr[s] = v.x * v.x + v.y * v.y;
    }
    float P[8], M[8];
    #pragma unroll
    for (int u = 0; u < 8; u++) {
        P[u] = pr[2 * u] + pr[2 * u + 1];
        M[u] = pr[2 * u] - pr[2 * u + 1];
    }
    float W15 = 0.f, W14 = 0.f, W12 = 0.f, W7 = 0.f;
    #pragma unroll
    for (int u = 0; u < 8; u++) {
        if (__popc(u) & 1)        { W15 -= M[u]; W14 -= P[u]; }
        else                      { W15 += M[u]; W14 += P[u]; }
        if (__popc(u >> 1) & 1)   W12 -= P[u]; else W12 += P[u];
        if (__popc(u & 3) & 1)    W7  -= M[u]; else W7  += M[u];
    }

    int xt = t ^ ((__popc(t) & 1) ? 0xC00 : 0);
    xt ^= xt >> 1; xt ^= xt >> 2; xt ^= xt >> 4; xt ^= xt >> 8;

    // per-thread signed z values -> smem (tree reduction instead of shfl:
    // ~3.3K CTA-wide FADD instead of 15.4K)
    #pragma unroll
    for (int w = 0; w < NQ; w++) {
        const int p = 11 - w;
        float Wv = (p == 11) ? W7 : (p == 10) ? W12 : (p == 9) ? W14 : W15;
        s_z[t * 13 + w] = ((xt >> p) & 1) ? -Wv : Wv;
    }
    __syncthreads();

    // stage B: 192 threads; thread (w + 12g) sums 16 rows for wire w
    if (t < 192) {
        int w = t % 12, g = t / 12;
        float acc = 0.f;
        #pragma unroll
        for (int k = 0; k < 16; k++) acc += s_z[(g * 16 + k) * 13 + w];
        s_p[w * 17 + g] = acc;
    }
    __syncthreads();

    // stage C: 12 threads finish the per-wire sums
    if (t < NQ) {
        float qv = 0.f;
        #pragma unroll
        for (int g = 0; g < 16; g++) qv += s_p[t * 17 + g];
        s_q[t] = qv;
    }
    __syncthreads();
    if (t < NQ) {
        float acc = db[t];
        #pragma unroll
        for (int w = 0; w < NQ; w++) acc += s_q[w] * dw[w * NQ + t];
        out[bidx * NQ + t] = tanhf(acc);
    }
}

extern "C" void kernel_launch(void* const* d_in, const int* in_sizes, int n_in,
                              void* d_out, int out_size) {
    const float* x  = (const float*)d_in[0];
    const float* qw = (const float*)d_in[1];
    const float* dw = (const float*)d_in[2];
    const float* db = (const float*)d_in[3];
    float* out = (float*)d_out;

    int batch = in_sizes[0] / NQ;

    precompute_gates<<<1, 256>>>(qw);
    qsim<<<batch, TPB>>>(x, dw, db, out);
}